// round 11
// baseline (speedup 1.0000x reference)
#include <cuda_runtime.h>
#include <cuda_fp16.h>
#include <mma.h>
#include <math.h>

using namespace nvcuda;

#define FULL 0xffffffffu

static const int NMAX = 50000;
static const int NPAD = 50048;          // 391 * 128
static const int CAP  = 192;            // bucket capacity (Poisson(32) tail ~1e-100)
static const long long EMAX = 1600000;

// ---------------- scratch (static __device__ — no allocation) ----------------
__device__ __align__(32) __half g_h1h[NPAD * 128];
__device__ __align__(32) __half g_l1h[NPAD * 128];
__device__ __align__(32) __half g_h2h[NPAD * 64];
__device__ __align__(16) float g_as1[NMAX * 4];
__device__ __align__(16) float g_ad1[NMAX * 4];
__device__ float g_as2[NMAX];
__device__ float g_ad2[NMAX];
__device__ int   g_cnt[NMAX];
__device__ int   g_srcs[NMAX * CAP];
__device__ int   g_is64;

// ---------------- init: zero counters + edge dtype detection ----------------
__global__ void init_k(const void* ei, int n, int* __restrict__ cnt) {
    int i = blockIdx.x * blockDim.x + threadIdx.x;
    if (i < n) cnt[i] = 0;
    if (blockIdx.x == 0 && threadIdx.x == 0) {
        const long long* p = (const long long*)ei;
        int ok = 1;
        for (int k = 0; k < 64; k++) {
            long long v = p[k];
            if (v < 0 || v >= (long long)n) { ok = 0; break; }
        }
        g_is64 = ok;
    }
}

__device__ __forceinline__ int edge_src(const void* ei, long long E, long long i) {
    return g_is64 ? (int)((const long long*)ei)[i] : ((const int*)ei)[i];
}
__device__ __forceinline__ int edge_dst(const void* ei, long long E, long long i) {
    return g_is64 ? (int)((const long long*)ei)[E + i] : ((const int*)ei)[E + i];
}

// ---------------- one-pass bucket scatter ----------------
__global__ void scat_k(const void* ei, long long E, int n, int* __restrict__ cnt,
                       int* __restrict__ srcs) {
    long long total = E + n;
    for (long long i = (long long)blockIdx.x * blockDim.x + threadIdx.x; i < total;
         i += (long long)gridDim.x * blockDim.x) {
        int s, d;
        if (i < E) { s = edge_src(ei, E, i); d = edge_dst(ei, E, i); }
        else { s = d = (int)(i - E); }
        int pos = atomicAdd(&cnt[d], 1);
        if (pos < CAP) srcs[d * CAP + pos] = s;
    }
}

// ---------------- GEMM1 (wmma) + fused alpha1 ----------------
__global__ __launch_bounds__(256)
void gemm1_k(const float* __restrict__ A, const float* __restrict__ W,
             const float* __restrict__ a_src, const float* __restrict__ a_dst,
             __half* __restrict__ Ch, float* __restrict__ asrc,
             float* __restrict__ adst, int n) {
    __shared__ __half As[2][128][48];
    __shared__ __half Bs[2][32][144];

    int tid = threadIdx.x;
    int wid = tid >> 5, lane = tid & 31;
    int wm = wid >> 2, wn = wid & 3;
    int row0 = blockIdx.x * 128;

    float4 va[4], vw[4];
    auto fetch = [&](int kc) {
#pragma unroll
        for (int q = 0; q < 4; q++) {
            int f = tid + q * 256;
            int r = f >> 3, c4 = f & 7;
            int gr = row0 + r;
            va[q] = (gr < n) ? *reinterpret_cast<const float4*>(&A[(size_t)gr * 128 + kc + c4 * 4])
                             : make_float4(0.f, 0.f, 0.f, 0.f);
        }
#pragma unroll
        for (int q = 0; q < 4; q++) {
            int f = tid + q * 256;
            int r = f >> 5, c4 = f & 31;
            vw[q] = *reinterpret_cast<const float4*>(&W[(size_t)(kc + r) * 128 + c4 * 4]);
        }
    };
    auto store = [&](int b) {
#pragma unroll
        for (int q = 0; q < 4; q++) {
            int f = tid + q * 256;
            int r = f >> 3, c = (f & 7) * 4;
            *reinterpret_cast<__half2*>(&As[b][r][c])     = __floats2half2_rn(va[q].x, va[q].y);
            *reinterpret_cast<__half2*>(&As[b][r][c + 2]) = __floats2half2_rn(va[q].z, va[q].w);
        }
#pragma unroll
        for (int q = 0; q < 4; q++) {
            int f = tid + q * 256;
            int r = f >> 5, c = (f & 31) * 4;
            *reinterpret_cast<__half2*>(&Bs[b][r][c])     = __floats2half2_rn(vw[q].x, vw[q].y);
            *reinterpret_cast<__half2*>(&Bs[b][r][c + 2]) = __floats2half2_rn(vw[q].z, vw[q].w);
        }
    };

    wmma::fragment<wmma::accumulator, 16, 16, 16, float> cf[4][2];
#pragma unroll
    for (int i = 0; i < 4; i++)
#pragma unroll
        for (int j = 0; j < 2; j++) wmma::fill_fragment(cf[i][j], 0.f);

    fetch(0); store(0); __syncthreads();

#pragma unroll
    for (int it = 0; it < 4; it++) {
        int b = it & 1;
        if (it < 3) fetch((it + 1) * 32);
#pragma unroll
        for (int kk = 0; kk < 32; kk += 16) {
            wmma::fragment<wmma::matrix_a, 16, 16, 16, __half, wmma::row_major> af[4];
            wmma::fragment<wmma::matrix_b, 16, 16, 16, __half, wmma::row_major> bf[2];
#pragma unroll
            for (int i = 0; i < 4; i++)
                wmma::load_matrix_sync(af[i], &As[b][wm * 64 + i * 16][kk], 48);
#pragma unroll
            for (int j = 0; j < 2; j++)
                wmma::load_matrix_sync(bf[j], &Bs[b][kk][wn * 32 + j * 16], 144);
#pragma unroll
            for (int i = 0; i < 4; i++)
#pragma unroll
                for (int j = 0; j < 2; j++)
                    wmma::mma_sync(cf[i][j], af[i], bf[j], cf[i][j]);
        }
        if (it < 3) store(b ^ 1);
        __syncthreads();
    }

    float (*cs)[16][20] = reinterpret_cast<float (*)[16][20]>(&As[0][0][0]);
    int r = lane >> 1, hh = lane & 1;
#pragma unroll
    for (int i = 0; i < 4; i++) {
        float asum = 0.f, dsum = 0.f;
#pragma unroll
        for (int j = 0; j < 2; j++) {
            wmma::store_matrix_sync(&cs[wid][0][0], cf[i][j], 20, wmma::mem_row_major);
            __syncwarp();
            const float* rp = &cs[wid][r][hh * 8];
            __half2 o[4];
#pragma unroll
            for (int t = 0; t < 4; t++) {
                float w0 = rp[2 * t], w1 = rp[2 * t + 1];
                o[t] = __floats2half2_rn(w0, w1);
                int c = wn * 32 + j * 16 + hh * 8 + 2 * t;
                asum += w0 * __ldg(&a_src[c]) + w1 * __ldg(&a_src[c + 1]);
                dsum += w0 * __ldg(&a_dst[c]) + w1 * __ldg(&a_dst[c + 1]);
            }
            *reinterpret_cast<uint4*>(
                &Ch[(size_t)(row0 + wm * 64 + i * 16 + r) * 128 + wn * 32 + j * 16 + hh * 8]) =
                *reinterpret_cast<uint4*>(o);
            __syncwarp();
        }
        asum += __shfl_xor_sync(FULL, asum, 1);
        dsum += __shfl_xor_sync(FULL, dsum, 1);
        int gr = row0 + wm * 64 + i * 16 + r;
        if (hh == 0 && gr < n) {
            asrc[gr * 4 + wn] = asum;
            adst[gr * 4 + wn] = dsum;
        }
    }
}

// ---------------- GEMM2 (wmma) + fused alpha2 ----------------
__global__ __launch_bounds__(256)
void gemm2_k(const __half* __restrict__ Ah, const float* __restrict__ W,
             const float* __restrict__ a_src, const float* __restrict__ a_dst,
             __half* __restrict__ Ch, float* __restrict__ asrc,
             float* __restrict__ adst, int n) {
    __shared__ __half As[2][128][48];
    __shared__ __half Bs[2][32][80];
    __shared__ float spa[128][2], spd[128][2];

    int tid = threadIdx.x;
    int wid = tid >> 5, lane = tid & 31;
    int wm = wid >> 1, wn = wid & 1;
    int row0 = blockIdx.x * 128;

    uint2 va[4]; float4 vw[2];
    auto fetch = [&](int kc) {
#pragma unroll
        for (int q = 0; q < 4; q++) {
            int f = tid + q * 256;
            int r = f >> 3, c4 = f & 7;
            int gr = row0 + r;
            va[q] = (gr < n) ? *reinterpret_cast<const uint2*>(&Ah[(size_t)gr * 128 + kc + c4 * 4])
                             : make_uint2(0u, 0u);
        }
#pragma unroll
        for (int q = 0; q < 2; q++) {
            int f = tid + q * 256;
            int r = f >> 4, c4 = f & 15;
            vw[q] = *reinterpret_cast<const float4*>(&W[(size_t)(kc + r) * 64 + c4 * 4]);
        }
    };
    auto store = [&](int b) {
#pragma unroll
        for (int q = 0; q < 4; q++) {
            int f = tid + q * 256;
            int r = f >> 3, c = (f & 7) * 4;
            *reinterpret_cast<uint2*>(&As[b][r][c]) = va[q];
        }
#pragma unroll
        for (int q = 0; q < 2; q++) {
            int f = tid + q * 256;
            int r = f >> 4, c = (f & 15) * 4;
            *reinterpret_cast<__half2*>(&Bs[b][r][c])     = __floats2half2_rn(vw[q].x, vw[q].y);
            *reinterpret_cast<__half2*>(&Bs[b][r][c + 2]) = __floats2half2_rn(vw[q].z, vw[q].w);
        }
    };

    wmma::fragment<wmma::accumulator, 16, 16, 16, float> cf[2][2];
#pragma unroll
    for (int i = 0; i < 2; i++)
#pragma unroll
        for (int j = 0; j < 2; j++) wmma::fill_fragment(cf[i][j], 0.f);

    fetch(0); store(0); __syncthreads();

#pragma unroll
    for (int it = 0; it < 4; it++) {
        int b = it & 1;
        if (it < 3) fetch((it + 1) * 32);
#pragma unroll
        for (int kk = 0; kk < 32; kk += 16) {
            wmma::fragment<wmma::matrix_a, 16, 16, 16, __half, wmma::row_major> af[2];
            wmma::fragment<wmma::matrix_b, 16, 16, 16, __half, wmma::row_major> bf[2];
#pragma unroll
            for (int i = 0; i < 2; i++)
                wmma::load_matrix_sync(af[i], &As[b][wm * 32 + i * 16][kk], 48);
#pragma unroll
            for (int j = 0; j < 2; j++)
                wmma::load_matrix_sync(bf[j], &Bs[b][kk][wn * 32 + j * 16], 80);
#pragma unroll
            for (int i = 0; i < 2; i++)
#pragma unroll
                for (int j = 0; j < 2; j++)
                    wmma::mma_sync(cf[i][j], af[i], bf[j], cf[i][j]);
        }
        if (it < 3) store(b ^ 1);
        __syncthreads();
    }

    float (*cs)[16][20] = reinterpret_cast<float (*)[16][20]>(&As[0][0][0]);
    int r = lane >> 1, hh = lane & 1;
#pragma unroll
    for (int i = 0; i < 2; i++) {
        float asum = 0.f, dsum = 0.f;
#pragma unroll
        for (int j = 0; j < 2; j++) {
            wmma::store_matrix_sync(&cs[wid][0][0], cf[i][j], 20, wmma::mem_row_major);
            __syncwarp();
            const float* rp = &cs[wid][r][hh * 8];
            __half2 o[4];
#pragma unroll
            for (int t = 0; t < 4; t++) {
                float w0 = rp[2 * t], w1 = rp[2 * t + 1];
                o[t] = __floats2half2_rn(w0, w1);
                int c = wn * 32 + j * 16 + hh * 8 + 2 * t;
                asum += w0 * __ldg(&a_src[c]) + w1 * __ldg(&a_src[c + 1]);
                dsum += w0 * __ldg(&a_dst[c]) + w1 * __ldg(&a_dst[c + 1]);
            }
            *reinterpret_cast<uint4*>(
                &Ch[(size_t)(row0 + wm * 32 + i * 16 + r) * 64 + wn * 32 + j * 16 + hh * 8]) =
                *reinterpret_cast<uint4*>(o);
            __syncwarp();
        }
        asum += __shfl_xor_sync(FULL, asum, 1);
        dsum += __shfl_xor_sync(FULL, dsum, 1);
        int lr = wm * 32 + i * 16 + r;
        if (hh == 0) { spa[lr][wn] = asum; spd[lr][wn] = dsum; }
    }
    __syncthreads();
    if (tid < 128) {
        int gr = row0 + tid;
        if (gr < n) {
            asrc[gr] = spa[tid][0] + spa[tid][1];
            adst[gr] = spd[tid][0] + spd[tid][1];
        }
    }
}

// ---------------- layer1 aggregation: TWO warps per dst node ----------------
// warp gw handles node v = gw>>1, head-pair hp = gw&1 (heads 2hp, 2hp+1 =
// channels [64hp, 64hp+64)). Lane owns 2 channels (one half2) -> warp gather
// is 32 x half2 = 128 B = 1 cache line per edge.
// staging: sq[wl][hsel][33] of float2 {q, src_bits}; padded rows (264 B) so the
// two head rows hit different banks. One LDS.64 broadcast per edge per lane.
#define AEDGE1(J) { \
    float2 t = sq[wl][hsel][(J)]; \
    float q  = t.x; \
    int   sj = __float_as_int(t.y); \
    __half2 hv = hf2[(size_t)sj * 64 + choff + lane]; \
    float2 f = __half22float2(hv); \
    a.x = fmaf(q, f.x, a.x); a.y = fmaf(q, f.y, a.y); \
    den += q; }

__global__ __launch_bounds__(256)
void agg1_k(const __half* __restrict__ hfeat, const float* __restrict__ asrc,
            const float* __restrict__ adst, const int* __restrict__ cnt,
            const int* __restrict__ srcs, const float* __restrict__ b1,
            __half* __restrict__ out, int n) {
    __shared__ float2 sq[8][2][33];
    const __half2* hf2 = reinterpret_cast<const __half2*>(hfeat);

    int gw   = (blockIdx.x * blockDim.x + threadIdx.x) >> 5;
    int wl   = (threadIdx.x >> 5);
    int lane = threadIdx.x & 31;
    int v    = gw >> 1;
    int hp   = gw & 1;
    if (v >= n) return;

    int hsel  = lane >> 4;               // head within pair
    int choff = hp * 32;                 // half2 offset of this warp's 64 channels
    float2 bb = *reinterpret_cast<const float2*>(&b1[hp * 64 + 2 * lane]);
    float2 ad = *reinterpret_cast<const float2*>(&adst[v * 4 + hp * 2]);

    int deg = min(cnt[v], CAP);
    int s0 = v * CAP;
    float den = 0.f;
    float2 a = {0.f, 0.f};

    for (int base = 0; base < deg; base += 32) {
        int i = base + lane;
        float q0 = 0.f, q1 = 0.f;
        int src = 0;
        if (i < deg) {
            src = srcs[s0 + i];
            float2 as = *reinterpret_cast<const float2*>(&asrc[src * 4 + hp * 2]);
            float e;
            e = as.x + ad.x; e = e > 0.f ? e : 0.2f * e; q0 = __expf(e);
            e = as.y + ad.y; e = e > 0.f ? e : 0.2f * e; q1 = __expf(e);
        }
        __syncwarp();                    // prior reads done before overwrite
        sq[wl][0][lane] = make_float2(q0, __int_as_float(src));
        sq[wl][1][lane] = make_float2(q1, __int_as_float(src));
        __syncwarp();
        int c = min(32, deg - base);
        int j = 0;
        for (; j + 4 <= c; j += 4) {
            AEDGE1(j) AEDGE1(j + 1) AEDGE1(j + 2) AEDGE1(j + 3)
        }
        for (; j < c; j++) AEDGE1(j)
    }
    float rd = 1.f / (den + 1e-16f);
    __half2 ov = __floats2half2_rn(fmaxf(a.x * rd + bb.x, 0.f),
                                   fmaxf(a.y * rd + bb.y, 0.f));
    reinterpret_cast<__half2*>(out + (size_t)v * 128)[choff + lane] = ov;
}

// ---------------- layer2 aggregation (1 head, 64 ch) ----------------
#define AEDGE2(J) { \
    float2 t = sq[wl][(J)]; \
    float q  = t.x; \
    int   sj = __float_as_int(t.y); \
    __half2 hv = hf2[(size_t)sj * 32 + lane]; \
    float2 f = __half22float2(hv); \
    a.x = fmaf(q, f.x, a.x); a.y = fmaf(q, f.y, a.y); \
    den += q; }

__global__ __launch_bounds__(256)
void agg2_k(const __half* __restrict__ hfeat, const float* __restrict__ asrc,
            const float* __restrict__ adst, const int* __restrict__ cnt,
            const int* __restrict__ srcs, const float* __restrict__ b2,
            float* __restrict__ out, int n) {
    __shared__ float2 sq[8][32];
    const __half2* hf2 = reinterpret_cast<const __half2*>(hfeat);

    int warp = (blockIdx.x * blockDim.x + threadIdx.x) >> 5;
    int wl   = (threadIdx.x >> 5);
    int lane = threadIdx.x & 31;
    int nw = (gridDim.x * blockDim.x) >> 5;
    float2 b = reinterpret_cast<const float2*>(b2)[lane];

    for (int v = warp; v < n; v += nw) {
        int deg = min(cnt[v], CAP);
        int s0 = v * CAP;
        float ad = adst[v];
        float den = 0.f;
        float2 a = {0.f, 0.f};

        for (int base = 0; base < deg; base += 32) {
            int i = base + lane;
            float p = 0.f;
            int src = 0;
            if (i < deg) {
                src = srcs[s0 + i];
                float e = asrc[src] + ad;
                e = e > 0.f ? e : 0.2f * e;
                p = __expf(e);
            }
            __syncwarp();
            sq[wl][lane] = make_float2(p, __int_as_float(src));
            __syncwarp();
            int c = min(32, deg - base);
            int j = 0;
            for (; j + 4 <= c; j += 4) {
                AEDGE2(j) AEDGE2(j + 1) AEDGE2(j + 2) AEDGE2(j + 3)
            }
            for (; j < c; j++) AEDGE2(j)
        }
        float rd = 1.f / (den + 1e-16f);
        float2 o;
        o.x = a.x * rd + b.x;
        o.y = a.y * rd + b.y;
        reinterpret_cast<float2*>(out + (size_t)v * 64)[lane] = o;
    }
}

// ---------------- launch ----------------
extern "C" void kernel_launch(void* const* d_in, const int* in_sizes, int n_in,
                              void* d_out, int out_size) {
    const float* x   = (const float*)d_in[0];
    const void*  ei  = d_in[1];
    const float* W1  = (const float*)d_in[2];
    const float* as1 = (const float*)d_in[3];
    const float* ad1 = (const float*)d_in[4];
    const float* b1  = (const float*)d_in[5];
    const float* W2  = (const float*)d_in[6];
    const float* as2 = (const float*)d_in[7];
    const float* ad2 = (const float*)d_in[8];
    const float* b2  = (const float*)d_in[9];
    float* out = (float*)d_out;

    int n = in_sizes[0] / 128;           // 50000
    long long E = in_sizes[1] / 2;       // 1600000

    __half *p_h1h, *p_l1h, *p_h2h;
    float *p_as1, *p_ad1, *p_as2, *p_ad2;
    int *p_cnt, *p_srcs;
    cudaGetSymbolAddress((void**)&p_h1h, g_h1h);
    cudaGetSymbolAddress((void**)&p_l1h, g_l1h);
    cudaGetSymbolAddress((void**)&p_h2h, g_h2h);
    cudaGetSymbolAddress((void**)&p_as1, g_as1);
    cudaGetSymbolAddress((void**)&p_ad1, g_ad1);
    cudaGetSymbolAddress((void**)&p_as2, g_as2);
    cudaGetSymbolAddress((void**)&p_ad2, g_ad2);
    cudaGetSymbolAddress((void**)&p_cnt, g_cnt);
    cudaGetSymbolAddress((void**)&p_srcs, g_srcs);

    int gemm_blocks  = (n + 127) / 128;
    int warp_blocks1 = (2 * n * 32 + 255) / 256;   // 2 warps per node
    int warp_blocks2 = (n * 32 + 255) / 256;

    cudaStream_t s2;
    cudaEvent_t ev1, ev2;
    cudaStreamCreateWithFlags(&s2, cudaStreamNonBlocking);
    cudaEventCreateWithFlags(&ev1, cudaEventDisableTiming);
    cudaEventCreateWithFlags(&ev2, cudaEventDisableTiming);

    cudaEventRecord(ev1, 0);
    cudaStreamWaitEvent(s2, ev1, 0);

    init_k<<<(n + 255) / 256, 256, 0, s2>>>(ei, n, p_cnt);
    scat_k<<<2048, 256, 0, s2>>>(ei, E, n, p_cnt, p_srcs);
    cudaEventRecord(ev2, s2);

    gemm1_k<<<gemm_blocks, 256>>>(x, W1, as1, ad1, p_h1h, p_as1, p_ad1, n);

    cudaStreamWaitEvent(0, ev2, 0);
    agg1_k<<<warp_blocks1, 256>>>(p_h1h, p_as1, p_ad1, p_cnt, p_srcs, b1, p_l1h, n);
    gemm2_k<<<gemm_blocks, 256>>>(p_l1h, W2, as2, ad2, p_h2h, p_as2, p_ad2, n);
    agg2_k<<<warp_blocks2, 256>>>(p_h2h, p_as2, p_ad2, p_cnt, p_srcs, b2, out, n);
}

// round 12
// speedup vs baseline: 1.2731x; 1.2731x over previous
#include <cuda_runtime.h>
#include <cuda_fp16.h>
#include <mma.h>
#include <math.h>

using namespace nvcuda;

#define FULL 0xffffffffu

static const int NMAX = 50000;
static const int NPAD = 50048;          // 391 * 128
static const int CAP  = 192;            // bucket capacity (Poisson(32) tail ~1e-100)
static const long long EMAX = 1600000;

// ---------------- scratch (static __device__ — no allocation) ----------------
__device__ __align__(32) __half g_h1h[NPAD * 128];
__device__ __align__(32) __half g_l1h[NPAD * 128];
__device__ __align__(32) __half g_h2h[NPAD * 64];
__device__ __align__(16) float g_as1[NMAX * 4];
__device__ __align__(16) float g_ad1[NMAX * 4];
__device__ float g_as2[NMAX];
__device__ float g_ad2[NMAX];
__device__ int   g_cnt[NMAX];
__device__ int   g_srcs[NMAX * CAP];
__device__ int   g_is64;

// ---------------- init: zero counters + edge dtype detection ----------------
__global__ void init_k(const void* ei, int n, int* __restrict__ cnt) {
    int i = blockIdx.x * blockDim.x + threadIdx.x;
    if (i < n) cnt[i] = 0;
    if (blockIdx.x == 0 && threadIdx.x == 0) {
        const long long* p = (const long long*)ei;
        int ok = 1;
        for (int k = 0; k < 64; k++) {
            long long v = p[k];
            if (v < 0 || v >= (long long)n) { ok = 0; break; }
        }
        g_is64 = ok;
    }
}

__device__ __forceinline__ int edge_src(const void* ei, long long E, long long i) {
    return g_is64 ? (int)((const long long*)ei)[i] : ((const int*)ei)[i];
}
__device__ __forceinline__ int edge_dst(const void* ei, long long E, long long i) {
    return g_is64 ? (int)((const long long*)ei)[E + i] : ((const int*)ei)[E + i];
}

// ---------------- one-pass bucket scatter ----------------
__global__ void scat_k(const void* ei, long long E, int n, int* __restrict__ cnt,
                       int* __restrict__ srcs) {
    long long total = E + n;
    for (long long i = (long long)blockIdx.x * blockDim.x + threadIdx.x; i < total;
         i += (long long)gridDim.x * blockDim.x) {
        int s, d;
        if (i < E) { s = edge_src(ei, E, i); d = edge_dst(ei, E, i); }
        else { s = d = (int)(i - E); }
        int pos = atomicAdd(&cnt[d], 1);
        if (pos < CAP) srcs[d * CAP + pos] = s;
    }
}

// ---------------- GEMM1 (wmma) + fused alpha1 ----------------
__global__ __launch_bounds__(256)
void gemm1_k(const float* __restrict__ A, const float* __restrict__ W,
             const float* __restrict__ a_src, const float* __restrict__ a_dst,
             __half* __restrict__ Ch, float* __restrict__ asrc,
             float* __restrict__ adst, int n) {
    __shared__ __half As[2][128][48];
    __shared__ __half Bs[2][32][144];

    int tid = threadIdx.x;
    int wid = tid >> 5, lane = tid & 31;
    int wm = wid >> 2, wn = wid & 3;
    int row0 = blockIdx.x * 128;

    float4 va[4], vw[4];
    auto fetch = [&](int kc) {
#pragma unroll
        for (int q = 0; q < 4; q++) {
            int f = tid + q * 256;
            int r = f >> 3, c4 = f & 7;
            int gr = row0 + r;
            va[q] = (gr < n) ? *reinterpret_cast<const float4*>(&A[(size_t)gr * 128 + kc + c4 * 4])
                             : make_float4(0.f, 0.f, 0.f, 0.f);
        }
#pragma unroll
        for (int q = 0; q < 4; q++) {
            int f = tid + q * 256;
            int r = f >> 5, c4 = f & 31;
            vw[q] = *reinterpret_cast<const float4*>(&W[(size_t)(kc + r) * 128 + c4 * 4]);
        }
    };
    auto store = [&](int b) {
#pragma unroll
        for (int q = 0; q < 4; q++) {
            int f = tid + q * 256;
            int r = f >> 3, c = (f & 7) * 4;
            *reinterpret_cast<__half2*>(&As[b][r][c])     = __floats2half2_rn(va[q].x, va[q].y);
            *reinterpret_cast<__half2*>(&As[b][r][c + 2]) = __floats2half2_rn(va[q].z, va[q].w);
        }
#pragma unroll
        for (int q = 0; q < 4; q++) {
            int f = tid + q * 256;
            int r = f >> 5, c = (f & 31) * 4;
            *reinterpret_cast<__half2*>(&Bs[b][r][c])     = __floats2half2_rn(vw[q].x, vw[q].y);
            *reinterpret_cast<__half2*>(&Bs[b][r][c + 2]) = __floats2half2_rn(vw[q].z, vw[q].w);
        }
    };

    wmma::fragment<wmma::accumulator, 16, 16, 16, float> cf[4][2];
#pragma unroll
    for (int i = 0; i < 4; i++)
#pragma unroll
        for (int j = 0; j < 2; j++) wmma::fill_fragment(cf[i][j], 0.f);

    fetch(0); store(0); __syncthreads();

#pragma unroll
    for (int it = 0; it < 4; it++) {
        int b = it & 1;
        if (it < 3) fetch((it + 1) * 32);
#pragma unroll
        for (int kk = 0; kk < 32; kk += 16) {
            wmma::fragment<wmma::matrix_a, 16, 16, 16, __half, wmma::row_major> af[4];
            wmma::fragment<wmma::matrix_b, 16, 16, 16, __half, wmma::row_major> bf[2];
#pragma unroll
            for (int i = 0; i < 4; i++)
                wmma::load_matrix_sync(af[i], &As[b][wm * 64 + i * 16][kk], 48);
#pragma unroll
            for (int j = 0; j < 2; j++)
                wmma::load_matrix_sync(bf[j], &Bs[b][kk][wn * 32 + j * 16], 144);
#pragma unroll
            for (int i = 0; i < 4; i++)
#pragma unroll
                for (int j = 0; j < 2; j++)
                    wmma::mma_sync(cf[i][j], af[i], bf[j], cf[i][j]);
        }
        if (it < 3) store(b ^ 1);
        __syncthreads();
    }

    float (*cs)[16][20] = reinterpret_cast<float (*)[16][20]>(&As[0][0][0]);
    int r = lane >> 1, hh = lane & 1;
#pragma unroll
    for (int i = 0; i < 4; i++) {
        float asum = 0.f, dsum = 0.f;
#pragma unroll
        for (int j = 0; j < 2; j++) {
            wmma::store_matrix_sync(&cs[wid][0][0], cf[i][j], 20, wmma::mem_row_major);
            __syncwarp();
            const float* rp = &cs[wid][r][hh * 8];
            __half2 o[4];
#pragma unroll
            for (int t = 0; t < 4; t++) {
                float w0 = rp[2 * t], w1 = rp[2 * t + 1];
                o[t] = __floats2half2_rn(w0, w1);
                int c = wn * 32 + j * 16 + hh * 8 + 2 * t;
                asum += w0 * __ldg(&a_src[c]) + w1 * __ldg(&a_src[c + 1]);
                dsum += w0 * __ldg(&a_dst[c]) + w1 * __ldg(&a_dst[c + 1]);
            }
            *reinterpret_cast<uint4*>(
                &Ch[(size_t)(row0 + wm * 64 + i * 16 + r) * 128 + wn * 32 + j * 16 + hh * 8]) =
                *reinterpret_cast<uint4*>(o);
            __syncwarp();
        }
        asum += __shfl_xor_sync(FULL, asum, 1);
        dsum += __shfl_xor_sync(FULL, dsum, 1);
        int gr = row0 + wm * 64 + i * 16 + r;
        if (hh == 0 && gr < n) {
            asrc[gr * 4 + wn] = asum;
            adst[gr * 4 + wn] = dsum;
        }
    }
}

// ---------------- GEMM2 (wmma) + fused alpha2 ----------------
__global__ __launch_bounds__(256)
void gemm2_k(const __half* __restrict__ Ah, const float* __restrict__ W,
             const float* __restrict__ a_src, const float* __restrict__ a_dst,
             __half* __restrict__ Ch, float* __restrict__ asrc,
             float* __restrict__ adst, int n) {
    __shared__ __half As[2][128][48];
    __shared__ __half Bs[2][32][80];
    __shared__ float spa[128][2], spd[128][2];

    int tid = threadIdx.x;
    int wid = tid >> 5, lane = tid & 31;
    int wm = wid >> 1, wn = wid & 1;
    int row0 = blockIdx.x * 128;

    uint2 va[4]; float4 vw[2];
    auto fetch = [&](int kc) {
#pragma unroll
        for (int q = 0; q < 4; q++) {
            int f = tid + q * 256;
            int r = f >> 3, c4 = f & 7;
            int gr = row0 + r;
            va[q] = (gr < n) ? *reinterpret_cast<const uint2*>(&Ah[(size_t)gr * 128 + kc + c4 * 4])
                             : make_uint2(0u, 0u);
        }
#pragma unroll
        for (int q = 0; q < 2; q++) {
            int f = tid + q * 256;
            int r = f >> 4, c4 = f & 15;
            vw[q] = *reinterpret_cast<const float4*>(&W[(size_t)(kc + r) * 64 + c4 * 4]);
        }
    };
    auto store = [&](int b) {
#pragma unroll
        for (int q = 0; q < 4; q++) {
            int f = tid + q * 256;
            int r = f >> 3, c = (f & 7) * 4;
            *reinterpret_cast<uint2*>(&As[b][r][c]) = va[q];
        }
#pragma unroll
        for (int q = 0; q < 2; q++) {
            int f = tid + q * 256;
            int r = f >> 4, c = (f & 15) * 4;
            *reinterpret_cast<__half2*>(&Bs[b][r][c])     = __floats2half2_rn(vw[q].x, vw[q].y);
            *reinterpret_cast<__half2*>(&Bs[b][r][c + 2]) = __floats2half2_rn(vw[q].z, vw[q].w);
        }
    };

    wmma::fragment<wmma::accumulator, 16, 16, 16, float> cf[2][2];
#pragma unroll
    for (int i = 0; i < 2; i++)
#pragma unroll
        for (int j = 0; j < 2; j++) wmma::fill_fragment(cf[i][j], 0.f);

    fetch(0); store(0); __syncthreads();

#pragma unroll
    for (int it = 0; it < 4; it++) {
        int b = it & 1;
        if (it < 3) fetch((it + 1) * 32);
#pragma unroll
        for (int kk = 0; kk < 32; kk += 16) {
            wmma::fragment<wmma::matrix_a, 16, 16, 16, __half, wmma::row_major> af[2];
            wmma::fragment<wmma::matrix_b, 16, 16, 16, __half, wmma::row_major> bf[2];
#pragma unroll
            for (int i = 0; i < 2; i++)
                wmma::load_matrix_sync(af[i], &As[b][wm * 32 + i * 16][kk], 48);
#pragma unroll
            for (int j = 0; j < 2; j++)
                wmma::load_matrix_sync(bf[j], &Bs[b][kk][wn * 32 + j * 16], 80);
#pragma unroll
            for (int i = 0; i < 2; i++)
#pragma unroll
                for (int j = 0; j < 2; j++)
                    wmma::mma_sync(cf[i][j], af[i], bf[j], cf[i][j]);
        }
        if (it < 3) store(b ^ 1);
        __syncthreads();
    }

    float (*cs)[16][20] = reinterpret_cast<float (*)[16][20]>(&As[0][0][0]);
    int r = lane >> 1, hh = lane & 1;
#pragma unroll
    for (int i = 0; i < 2; i++) {
        float asum = 0.f, dsum = 0.f;
#pragma unroll
        for (int j = 0; j < 2; j++) {
            wmma::store_matrix_sync(&cs[wid][0][0], cf[i][j], 20, wmma::mem_row_major);
            __syncwarp();
            const float* rp = &cs[wid][r][hh * 8];
            __half2 o[4];
#pragma unroll
            for (int t = 0; t < 4; t++) {
                float w0 = rp[2 * t], w1 = rp[2 * t + 1];
                o[t] = __floats2half2_rn(w0, w1);
                int c = wn * 32 + j * 16 + hh * 8 + 2 * t;
                asum += w0 * __ldg(&a_src[c]) + w1 * __ldg(&a_src[c + 1]);
                dsum += w0 * __ldg(&a_dst[c]) + w1 * __ldg(&a_dst[c + 1]);
            }
            *reinterpret_cast<uint4*>(
                &Ch[(size_t)(row0 + wm * 32 + i * 16 + r) * 64 + wn * 32 + j * 16 + hh * 8]) =
                *reinterpret_cast<uint4*>(o);
            __syncwarp();
        }
        asum += __shfl_xor_sync(FULL, asum, 1);
        dsum += __shfl_xor_sync(FULL, dsum, 1);
        int lr = wm * 32 + i * 16 + r;
        if (hh == 0) { spa[lr][wn] = asum; spd[lr][wn] = dsum; }
    }
    __syncthreads();
    if (tid < 128) {
        int gr = row0 + tid;
        if (gr < n) {
            asrc[gr] = spa[tid][0] + spa[tid][1];
            adst[gr] = spd[tid][0] + spd[tid][1];
        }
    }
}

// ---------------- layer1 aggregation: warp per dst, 8-wide batched inner loop ----
// R8 staging (conflict-free float4-broadcast + int-broadcast), but the inner loop
// loads 8 {q,src} pairs, then issues 8 independent gather LDG.64s, then consumes.
__global__ __launch_bounds__(256)
void agg1_k(const __half* __restrict__ hfeat, const float* __restrict__ asrc,
            const float* __restrict__ adst, const int* __restrict__ cnt,
            const int* __restrict__ srcs, const float* __restrict__ b1,
            __half* __restrict__ out, int n) {
    __shared__ float4 spm[8][32];
    __shared__ int    ssm[8][32];
    float* spf = reinterpret_cast<float*>(spm);
    const float2* hf2 = reinterpret_cast<const float2*>(hfeat);

    int warp = (blockIdx.x * blockDim.x + threadIdx.x) >> 5;
    int wl   = (threadIdx.x >> 5);
    int lane = threadIdx.x & 31;
    int nw = (gridDim.x * blockDim.x) >> 5;
    int hsel = lane >> 3;
    float4 bb = reinterpret_cast<const float4*>(b1)[lane];

    for (int v = warp; v < n; v += nw) {
        int deg = min(cnt[v], CAP);
        int s0 = v * CAP;
        float4 ad = reinterpret_cast<const float4*>(adst)[v];
        float den = 0.f;
        float4 acc = {0.f, 0.f, 0.f, 0.f};

        for (int base = 0; base < deg; base += 32) {
            int i = base + lane;
            float4 pv = {0.f, 0.f, 0.f, 0.f};
            int src = 0;
            if (i < deg) {
                src = srcs[s0 + i];
                float4 as = reinterpret_cast<const float4*>(asrc)[src];
                float e;
                e = as.x + ad.x; e = e > 0.f ? e : 0.2f * e; pv.x = __expf(e);
                e = as.y + ad.y; e = e > 0.f ? e : 0.2f * e; pv.y = __expf(e);
                e = as.z + ad.z; e = e > 0.f ? e : 0.2f * e; pv.z = __expf(e);
                e = as.w + ad.w; e = e > 0.f ? e : 0.2f * e; pv.w = __expf(e);
            }
            __syncwarp();                 // prior reads done before overwrite
            spm[wl][lane] = pv;
            ssm[wl][lane] = src;
            __syncwarp();
            int c = min(32, deg - base);
            int j = 0;
            for (; j + 8 <= c; j += 8) {
                float  qv[8];
                int    sv[8];
#pragma unroll
                for (int t = 0; t < 8; t++) {
                    qv[t] = spf[(wl << 7) + ((j + t) << 2) + hsel];
                    sv[t] = ssm[wl][j + t];
                }
                float2 rw[8];
#pragma unroll
                for (int t = 0; t < 8; t++)
                    rw[t] = hf2[(size_t)sv[t] * 32 + lane];
#pragma unroll
                for (int t = 0; t < 8; t++) {
                    float2 fa = __half22float2(*reinterpret_cast<__half2*>(&rw[t].x));
                    float2 fb = __half22float2(*reinterpret_cast<__half2*>(&rw[t].y));
                    acc.x = fmaf(qv[t], fa.x, acc.x);
                    acc.y = fmaf(qv[t], fa.y, acc.y);
                    acc.z = fmaf(qv[t], fb.x, acc.z);
                    acc.w = fmaf(qv[t], fb.y, acc.w);
                    den += qv[t];
                }
            }
            for (; j < c; j++) {
                float q = spf[(wl << 7) + (j << 2) + hsel];
                int  sj = ssm[wl][j];
                float2 raw = hf2[(size_t)sj * 32 + lane];
                float2 fa = __half22float2(*reinterpret_cast<__half2*>(&raw.x));
                float2 fb = __half22float2(*reinterpret_cast<__half2*>(&raw.y));
                acc.x = fmaf(q, fa.x, acc.x);
                acc.y = fmaf(q, fa.y, acc.y);
                acc.z = fmaf(q, fb.x, acc.z);
                acc.w = fmaf(q, fb.y, acc.w);
                den += q;
            }
        }
        float rd = 1.f / (den + 1e-16f);
        uint2 ov;
        *reinterpret_cast<__half2*>(&ov.x) =
            __floats2half2_rn(fmaxf(acc.x * rd + bb.x, 0.f), fmaxf(acc.y * rd + bb.y, 0.f));
        *reinterpret_cast<__half2*>(&ov.y) =
            __floats2half2_rn(fmaxf(acc.z * rd + bb.z, 0.f), fmaxf(acc.w * rd + bb.w, 0.f));
        reinterpret_cast<uint2*>(out + (size_t)v * 128)[lane] = ov;
    }
}

// ---------------- layer2 aggregation (1 head, 64 ch), 8-wide batched ----------------
__global__ __launch_bounds__(256)
void agg2_k(const __half* __restrict__ hfeat, const float* __restrict__ asrc,
            const float* __restrict__ adst, const int* __restrict__ cnt,
            const int* __restrict__ srcs, const float* __restrict__ b2,
            float* __restrict__ out, int n) {
    __shared__ float2 sq[8][32];
    const __half2* hf2 = reinterpret_cast<const __half2*>(hfeat);

    int warp = (blockIdx.x * blockDim.x + threadIdx.x) >> 5;
    int wl   = (threadIdx.x >> 5);
    int lane = threadIdx.x & 31;
    int nw = (gridDim.x * blockDim.x) >> 5;
    float2 b = reinterpret_cast<const float2*>(b2)[lane];

    for (int v = warp; v < n; v += nw) {
        int deg = min(cnt[v], CAP);
        int s0 = v * CAP;
        float ad = adst[v];
        float den = 0.f;
        float2 a = {0.f, 0.f};

        for (int base = 0; base < deg; base += 32) {
            int i = base + lane;
            float p = 0.f;
            int src = 0;
            if (i < deg) {
                src = srcs[s0 + i];
                float e = asrc[src] + ad;
                e = e > 0.f ? e : 0.2f * e;
                p = __expf(e);
            }
            __syncwarp();
            sq[wl][lane] = make_float2(p, __int_as_float(src));
            __syncwarp();
            int c = min(32, deg - base);
            int j = 0;
            for (; j + 8 <= c; j += 8) {
                float qv[8]; int sv[8];
#pragma unroll
                for (int t = 0; t < 8; t++) {
                    float2 tt = sq[wl][j + t];
                    qv[t] = tt.x;
                    sv[t] = __float_as_int(tt.y);
                }
                __half2 hv[8];
#pragma unroll
                for (int t = 0; t < 8; t++)
                    hv[t] = hf2[(size_t)sv[t] * 32 + lane];
#pragma unroll
                for (int t = 0; t < 8; t++) {
                    float2 f = __half22float2(hv[t]);
                    a.x = fmaf(qv[t], f.x, a.x);
                    a.y = fmaf(qv[t], f.y, a.y);
                    den += qv[t];
                }
            }
            for (; j < c; j++) {
                float2 t = sq[wl][j];
                float q = t.x;
                int  sj = __float_as_int(t.y);
                float2 f = __half22float2(hf2[(size_t)sj * 32 + lane]);
                a.x = fmaf(q, f.x, a.x);
                a.y = fmaf(q, f.y, a.y);
                den += q;
            }
        }
        float rd = 1.f / (den + 1e-16f);
        float2 o;
        o.x = a.x * rd + b.x;
        o.y = a.y * rd + b.y;
        reinterpret_cast<float2*>(out + (size_t)v * 64)[lane] = o;
    }
}

// ---------------- launch ----------------
extern "C" void kernel_launch(void* const* d_in, const int* in_sizes, int n_in,
                              void* d_out, int out_size) {
    const float* x   = (const float*)d_in[0];
    const void*  ei  = d_in[1];
    const float* W1  = (const float*)d_in[2];
    const float* as1 = (const float*)d_in[3];
    const float* ad1 = (const float*)d_in[4];
    const float* b1  = (const float*)d_in[5];
    const float* W2  = (const float*)d_in[6];
    const float* as2 = (const float*)d_in[7];
    const float* ad2 = (const float*)d_in[8];
    const float* b2  = (const float*)d_in[9];
    float* out = (float*)d_out;

    int n = in_sizes[0] / 128;           // 50000
    long long E = in_sizes[1] / 2;       // 1600000

    __half *p_h1h, *p_l1h, *p_h2h;
    float *p_as1, *p_ad1, *p_as2, *p_ad2;
    int *p_cnt, *p_srcs;
    cudaGetSymbolAddress((void**)&p_h1h, g_h1h);
    cudaGetSymbolAddress((void**)&p_l1h, g_l1h);
    cudaGetSymbolAddress((void**)&p_h2h, g_h2h);
    cudaGetSymbolAddress((void**)&p_as1, g_as1);
    cudaGetSymbolAddress((void**)&p_ad1, g_ad1);
    cudaGetSymbolAddress((void**)&p_as2, g_as2);
    cudaGetSymbolAddress((void**)&p_ad2, g_ad2);
    cudaGetSymbolAddress((void**)&p_cnt, g_cnt);
    cudaGetSymbolAddress((void**)&p_srcs, g_srcs);

    int gemm_blocks = (n + 127) / 128;
    int warp_blocks = (n * 32 + 255) / 256;

    cudaStream_t s2;
    cudaEvent_t ev1, ev2;
    cudaStreamCreateWithFlags(&s2, cudaStreamNonBlocking);
    cudaEventCreateWithFlags(&ev1, cudaEventDisableTiming);
    cudaEventCreateWithFlags(&ev2, cudaEventDisableTiming);

    cudaEventRecord(ev1, 0);
    cudaStreamWaitEvent(s2, ev1, 0);

    init_k<<<(n + 255) / 256, 256, 0, s2>>>(ei, n, p_cnt);
    scat_k<<<2048, 256, 0, s2>>>(ei, E, n, p_cnt, p_srcs);
    cudaEventRecord(ev2, s2);

    gemm1_k<<<gemm_blocks, 256>>>(x, W1, as1, ad1, p_h1h, p_as1, p_ad1, n);

    cudaStreamWaitEvent(0, ev2, 0);
    agg1_k<<<warp_blocks, 256>>>(p_h1h, p_as1, p_ad1, p_cnt, p_srcs, b1, p_l1h, n);
    gemm2_k<<<gemm_blocks, 256>>>(p_l1h, W2, as2, ad2, p_h2h, p_as2, p_ad2, n);
    agg2_k<<<warp_blocks, 256>>>(p_h2h, p_as2, p_ad2, p_cnt, p_srcs, b2, out, n);
}